// round 1
// baseline (speedup 1.0000x reference)
#include <cuda_runtime.h>

// Shapes (fixed by the problem instance)
#define B_   8
#define M_   8192
#define D_   1024
#define KSEG 4
#define MB_  2048            // M_/KSEG
#define POS  32
#define KIN  (D_ + POS)      // 1056
#define ROWS (B_ * MB_)      // 16384 output rows

// Scratch (device globals; no allocation allowed)
__device__ float g_pooled[ROWS * D_];   // 67 MB
__device__ float g_bias2[MB_ * D_];     // 8.4 MB

// ---------------------------------------------------------------------------
// Kernel 1: segment-mean pooling.  out_row = b*MB_+mb maps to input rows
// out_row*4 .. out_row*4+3 (since M_ = MB_*KSEG exactly; all counts == 4).
// Vectorized float4: 256 float4 per row.
// ---------------------------------------------------------------------------
__global__ __launch_bounds__(256) void pool_kernel(const float4* __restrict__ in) {
    size_t i = (size_t)blockIdx.x * 256 + threadIdx.x;     // out float4 idx
    int row = (int)(i >> 8);                               // /256
    int c   = (int)(i & 255);
    const float4* p = in + ((size_t)row * 4) * 256 + c;
    float4 a = p[0], b = p[256], d = p[512], e = p[768];
    float4 o;
    o.x = 0.25f * (a.x + b.x + d.x + e.x);
    o.y = 0.25f * (a.y + b.y + d.y + e.y);
    o.z = 0.25f * (a.z + b.z + d.z + e.z);
    o.w = 0.25f * (a.w + b.w + d.w + e.w);
    reinterpret_cast<float4*>(g_pooled)[i] = o;
}

// ---------------------------------------------------------------------------
// Kernel 2: bias2[mb, o] = b[o] + sum_j ff(mb)[j] * W[o, 1024 + j]
// ff: half=16 freqs = exp(linspace(0, ln 1000, 16)); sin then cos.
// One block per mb; ff computed once into shared.
// ---------------------------------------------------------------------------
__global__ __launch_bounds__(256) void bias2_kernel(const float* __restrict__ W,
                                                    const float* __restrict__ bias) {
    __shared__ float ff[POS];
    int mb  = blockIdx.x;
    int tid = threadIdx.x;
    if (tid < 16) {
        float pos  = (float)mb / (float)(MB_ - 1);          // already in [0,1]
        float freq = expf((float)tid * (6.907755278982137f / 15.0f));
        float ang  = pos * freq;
        ff[tid]      = sinf(ang);
        ff[tid + 16] = cosf(ang);
    }
    __syncthreads();
    #pragma unroll
    for (int r = 0; r < 4; ++r) {
        int o = tid + r * 256;
        const float* wrow = W + (size_t)o * KIN + D_;
        float acc = bias[o];
        #pragma unroll
        for (int j = 0; j < POS; ++j) acc += ff[j] * wrow[j];
        g_bias2[(size_t)mb * D_ + o] = acc;
    }
}

// ---------------------------------------------------------------------------
// Kernel 3: SGEMM  C[ROWS,1024] = pooled[ROWS,1024] @ W[:, :1024]^T + bias2
// (both operands K-major / "NT").  128x128x16 tiles, 256 threads, 8x8 micro.
// ---------------------------------------------------------------------------
#define BM 128
#define BN 128
#define BK 16

__global__ __launch_bounds__(256) void gemm_kernel(const float* __restrict__ W,
                                                   float* __restrict__ C) {
    __shared__ float As[BK][BM];
    __shared__ float Bs[BK][BN];

    const int tid = threadIdx.x;
    const int tx  = tid & 15;          // N direction (8 cols)
    const int ty  = tid >> 4;          // M direction (8 rows)

    const float* Ablk = g_pooled + (size_t)blockIdx.y * BM * D_;
    const float* Wblk = W        + (size_t)blockIdx.x * BN * KIN;

    // load mapping: 128 rows x 16 k = 512 float4, 2 per thread
    const int lrow  = tid >> 2;        // 0..63
    const int lcol4 = (tid & 3) * 4;   // 0,4,8,12

    float acc[8][8];
    #pragma unroll
    for (int i = 0; i < 8; ++i)
        #pragma unroll
        for (int j = 0; j < 8; ++j) acc[i][j] = 0.0f;

    for (int k0 = 0; k0 < D_; k0 += BK) {
        #pragma unroll
        for (int r = 0; r < 2; ++r) {
            int row = lrow + r * 64;
            float4 va = *reinterpret_cast<const float4*>(Ablk + (size_t)row * D_  + k0 + lcol4);
            As[lcol4 + 0][row] = va.x;
            As[lcol4 + 1][row] = va.y;
            As[lcol4 + 2][row] = va.z;
            As[lcol4 + 3][row] = va.w;
            float4 vb = *reinterpret_cast<const float4*>(Wblk + (size_t)row * KIN + k0 + lcol4);
            Bs[lcol4 + 0][row] = vb.x;
            Bs[lcol4 + 1][row] = vb.y;
            Bs[lcol4 + 2][row] = vb.z;
            Bs[lcol4 + 3][row] = vb.w;
        }
        __syncthreads();

        #pragma unroll
        for (int k = 0; k < BK; ++k) {
            float a[8], b[8];
            *reinterpret_cast<float4*>(&a[0]) = *reinterpret_cast<const float4*>(&As[k][ty * 8]);
            *reinterpret_cast<float4*>(&a[4]) = *reinterpret_cast<const float4*>(&As[k][ty * 8 + 4]);
            *reinterpret_cast<float4*>(&b[0]) = *reinterpret_cast<const float4*>(&Bs[k][tx * 8]);
            *reinterpret_cast<float4*>(&b[4]) = *reinterpret_cast<const float4*>(&Bs[k][tx * 8 + 4]);
            #pragma unroll
            for (int i = 0; i < 8; ++i)
                #pragma unroll
                for (int j = 0; j < 8; ++j)
                    acc[i][j] += a[i] * b[j];
        }
        __syncthreads();
    }

    // epilogue: + bias2[row & (MB_-1), o]
    const int row0 = blockIdx.y * BM + ty * 8;
    const int col0 = blockIdx.x * BN + tx * 8;
    #pragma unroll
    for (int i = 0; i < 8; ++i) {
        int row = row0 + i;
        const float* b2 = g_bias2 + (size_t)(row & (MB_ - 1)) * D_ + col0;
        float* cptr = C + (size_t)row * D_ + col0;
        float4 r0, r1;
        r0.x = acc[i][0] + b2[0]; r0.y = acc[i][1] + b2[1];
        r0.z = acc[i][2] + b2[2]; r0.w = acc[i][3] + b2[3];
        r1.x = acc[i][4] + b2[4]; r1.y = acc[i][5] + b2[5];
        r1.z = acc[i][6] + b2[6]; r1.w = acc[i][7] + b2[7];
        *reinterpret_cast<float4*>(cptr)     = r0;
        *reinterpret_cast<float4*>(cptr + 4) = r1;
    }
}

// ---------------------------------------------------------------------------
extern "C" void kernel_launch(void* const* d_in, const int* in_sizes, int n_in,
                              void* d_out, int out_size) {
    const float* beat = (const float*)d_in[0];   // [8, 8192, 1024]
    const float* W    = (const float*)d_in[1];   // [1024, 1056]
    const float* bias = (const float*)d_in[2];   // [1024]
    float* out = (float*)d_out;                  // [8, 2048, 1024]

    // 1) pooling: ROWS*D_/4 float4 elements / 256 threads
    pool_kernel<<<(ROWS * (D_ / 4)) / 256, 256>>>((const float4*)beat);

    // 2) fourier bias
    bias2_kernel<<<MB_, 256>>>(W, bias);

    // 3) main GEMM
    dim3 grid(D_ / BN, ROWS / BM);
    gemm_kernel<<<grid, 256>>>(W, out);
}

// round 3
// speedup vs baseline: 1.9096x; 1.9096x over previous
#include <cuda_runtime.h>
#include <cuda_bf16.h>
#include <cstdint>

// ---------------------------------------------------------------------------
// Shapes (fixed by the problem instance)
#define B_   8
#define M_   8192
#define D_   1024
#define MB_  2048
#define POS  32
#define KIN  1056
#define ROWS 16384          // B_*MB_
#define KSPL 3072           // 3 * D_  (hi | lo | hi split blocks)

// Scratch (device globals; no allocation allowed)
__device__ __align__(256) __nv_bfloat16 g_A [(size_t)ROWS * KSPL]; // ~101 MB
__device__ __align__(256) __nv_bfloat16 g_Ws[(size_t)D_   * KSPL]; //  ~6.3 MB
__device__ __align__(256) float         g_bias2[MB_ * D_];         //  ~8.4 MB

// ---------------------------------------------------------------------------
// PTX helpers (all baseline sm_80+ features: cp.async, ldmatrix, mma.sync)
// ---------------------------------------------------------------------------
__device__ __forceinline__ uint32_t smem_u32(const void* p) {
    uint32_t a;
    asm("{ .reg .u64 t; cvta.to.shared.u64 t, %1; cvt.u32.u64 %0, t; }" : "=r"(a) : "l"(p));
    return a;
}
#define CP16(dst, src) \
    asm volatile("cp.async.cg.shared.global [%0], [%1], 16;" :: "r"(dst), "l"(src) : "memory")
#define CP_COMMIT() asm volatile("cp.async.commit_group;" ::: "memory")
#define CP_WAIT(n)  asm volatile("cp.async.wait_group %0;" :: "n"(n) : "memory")
#define LDSM4(r0, r1, r2, r3, a) \
    asm volatile("ldmatrix.sync.aligned.m8n8.x4.shared.b16 {%0,%1,%2,%3}, [%4];" \
        : "=r"(r0), "=r"(r1), "=r"(r2), "=r"(r3) : "r"(a))
#define MMA16816(d, a, b) \
    asm volatile("mma.sync.aligned.m16n8k16.row.col.f32.bf16.bf16.f32 " \
        "{%0,%1,%2,%3}, {%4,%5,%6,%7}, {%8,%9}, {%0,%1,%2,%3};" \
        : "+f"((d)[0]), "+f"((d)[1]), "+f"((d)[2]), "+f"((d)[3]) \
        : "r"((a)[0]), "r"((a)[1]), "r"((a)[2]), "r"((a)[3]), "r"((b)[0]), "r"((b)[1]))

#define SWZ(x) ((x) ^ (((x) >> 3) & 0x70))

__device__ __forceinline__ void bf16_split(float x, unsigned short& h, unsigned short& l) {
    __nv_bfloat16 hb = __float2bfloat16(x);
    __nv_bfloat16 lb = __float2bfloat16(x - __bfloat162float(hb));
    h = __bfloat16_as_ushort(hb);
    l = __bfloat16_as_ushort(lb);
}

// ---------------------------------------------------------------------------
// Kernel 1: 4-row mean pool + bf16 hi/lo split.  A' = [hi | lo | hi], K=3072
// ---------------------------------------------------------------------------
__global__ __launch_bounds__(256) void pool_split_kernel(const float4* __restrict__ in) {
    size_t i = (size_t)blockIdx.x * 256 + threadIdx.x;   // one float4 of one out row
    int row = (int)(i >> 8);
    int c4  = (int)(i & 255);
    const float4* p = in + ((size_t)row * 4) * 256 + c4;
    float4 a = p[0], b = p[256], d = p[512], e = p[768];
    float m0 = 0.25f * (a.x + b.x + d.x + e.x);
    float m1 = 0.25f * (a.y + b.y + d.y + e.y);
    float m2 = 0.25f * (a.z + b.z + d.z + e.z);
    float m3 = 0.25f * (a.w + b.w + d.w + e.w);
    unsigned short h0, h1, h2, h3, l0, l1, l2, l3;
    bf16_split(m0, h0, l0); bf16_split(m1, h1, l1);
    bf16_split(m2, h2, l2); bf16_split(m3, h3, l3);
    uint2 hp, lp;
    hp.x = (uint32_t)h0 | ((uint32_t)h1 << 16);  hp.y = (uint32_t)h2 | ((uint32_t)h3 << 16);
    lp.x = (uint32_t)l0 | ((uint32_t)l1 << 16);  lp.y = (uint32_t)l2 | ((uint32_t)l3 << 16);
    __nv_bfloat16* base = g_A + (size_t)row * KSPL + c4 * 4;
    *reinterpret_cast<uint2*>(base)        = hp;   // block 0: hi
    *reinterpret_cast<uint2*>(base + 1024) = lp;   // block 1: lo
    *reinterpret_cast<uint2*>(base + 2048) = hp;   // block 2: hi
}

// ---------------------------------------------------------------------------
// Kernel 2: W split.  W' = [hi | hi | lo]  (A_hi*W_hi + A_lo*W_hi + A_hi*W_lo)
// ---------------------------------------------------------------------------
__global__ __launch_bounds__(256) void wsplit_kernel(const float* __restrict__ W) {
    int i  = blockIdx.x * 256 + threadIdx.x;   // over 1024 * 256
    int o  = i >> 8;
    int c4 = i & 255;
    float4 w = *reinterpret_cast<const float4*>(W + (size_t)o * KIN + c4 * 4);
    unsigned short h0, h1, h2, h3, l0, l1, l2, l3;
    bf16_split(w.x, h0, l0); bf16_split(w.y, h1, l1);
    bf16_split(w.z, h2, l2); bf16_split(w.w, h3, l3);
    uint2 hp, lp;
    hp.x = (uint32_t)h0 | ((uint32_t)h1 << 16);  hp.y = (uint32_t)h2 | ((uint32_t)h3 << 16);
    lp.x = (uint32_t)l0 | ((uint32_t)l1 << 16);  lp.y = (uint32_t)l2 | ((uint32_t)l3 << 16);
    __nv_bfloat16* base = g_Ws + (size_t)o * KSPL + c4 * 4;
    *reinterpret_cast<uint2*>(base)        = hp;
    *reinterpret_cast<uint2*>(base + 1024) = hp;
    *reinterpret_cast<uint2*>(base + 2048) = lp;
}

// ---------------------------------------------------------------------------
// Kernel 3: fourier bias (fp32 exact): bias2[mb,o] = b[o] + ff(mb)·W[o,1024:]
// ---------------------------------------------------------------------------
__global__ __launch_bounds__(256) void bias2_kernel(const float* __restrict__ W,
                                                    const float* __restrict__ bias) {
    __shared__ float ff[POS];
    int mb  = blockIdx.x;
    int tid = threadIdx.x;
    if (tid < 16) {
        float pos  = (float)mb / (float)(MB_ - 1);
        float freq = expf((float)tid * (6.907755278982137f / 15.0f));
        float ang  = pos * freq;
        ff[tid]      = sinf(ang);
        ff[tid + 16] = cosf(ang);
    }
    __syncthreads();
    #pragma unroll
    for (int r = 0; r < 4; ++r) {
        int o = tid + r * 256;
        const float* wrow = W + (size_t)o * KIN + D_;
        float acc = bias[o];
        #pragma unroll
        for (int j = 0; j < POS; ++j) acc += ff[j] * wrow[j];
        g_bias2[(size_t)mb * D_ + o] = acc;
    }
}

// ---------------------------------------------------------------------------
// Kernel 4: bf16 mma.sync GEMM.  C[16384,1024] = A'[.,3072] @ W'[1024,3072]^T
// 128x128x64 tiles, 3-stage cp.async, SW128 smem, ldmatrix, 8 warps (2x4),
// warp tile 64x32, fp32 accumulators, fused bias2 epilogue.
// ---------------------------------------------------------------------------
#define BM 128
#define BN 128
#define BK 64
#define NKC 48               // 3072 / 64
#define STAGES 3
#define TILE_B (BM * BK * 2) // 16 KB (A or B half)
#define STG_B  (2 * TILE_B)  // 32 KB per stage
#define SMEM_TOTAL (STAGES * STG_B)  // 96 KB

extern __shared__ char dynsmem[];

__global__ __launch_bounds__(256, 1) void gemm_kernel(float* __restrict__ C) {
    const uint32_t sb = smem_u32(dynsmem);
    const int tid  = threadIdx.x;
    const int lane = tid & 31;
    const int wid  = tid >> 5;
    const int wm   = wid >> 2;          // 0..1  (M dir, 64 rows)
    const int wn   = wid & 3;           // 0..3  (N dir, 32 cols)
    const int m0 = blockIdx.y * BM;
    const int n0 = blockIdx.x * BN;

    // global load pointers: thread covers 4 16B chunks of A and 4 of B per tile
    const int grow = tid >> 3;          // 0..31 base row (stride 32)
    const int gseg = tid & 7;           // 16B segment within 128B row
    const __nv_bfloat16* gA = g_A  + (size_t)(m0 + grow) * KSPL + gseg * 8;
    const __nv_bfloat16* gB = g_Ws + (size_t)(n0 + grow) * KSPL + gseg * 8;
    const uint32_t soff = SWZ((uint32_t)(grow * 128 + gseg * 16));

    float acc[4][4][4];
    #pragma unroll
    for (int i = 0; i < 4; ++i)
        #pragma unroll
        for (int j = 0; j < 4; ++j)
            #pragma unroll
            for (int v = 0; v < 4; ++v) acc[i][j][v] = 0.0f;

    // ---- prologue: prefetch STAGES-1 tiles --------------------------------
    #pragma unroll
    for (int s = 0; s < STAGES - 1; ++s) {
        const uint32_t sa = sb + s * STG_B;
        #pragma unroll
        for (int r = 0; r < 4; ++r) {
            CP16(sa + SWZ((uint32_t)((grow + r * 32) * 128 + gseg * 16)),
                 gA + (size_t)(r * 32) * KSPL + s * 64);
            CP16(sa + TILE_B + SWZ((uint32_t)((grow + r * 32) * 128 + gseg * 16)),
                 gB + (size_t)(r * 32) * KSPL + s * 64);
        }
        CP_COMMIT();
    }

    // ---- mainloop ---------------------------------------------------------
    for (int kc = 0; kc < NKC; ++kc) {
        CP_WAIT(STAGES - 2);
        __syncthreads();

        // issue loads for tile kc+STAGES-1 into stage (kc+STAGES-1)%STAGES
        const int kn = kc + STAGES - 1;
        if (kn < NKC) {
            const uint32_t sa = sb + (kn % STAGES) * STG_B;
            #pragma unroll
            for (int r = 0; r < 4; ++r) {
                CP16(sa + SWZ((uint32_t)((grow + r * 32) * 128 + gseg * 16)),
                     gA + (size_t)(r * 32) * KSPL + kn * 64);
                CP16(sa + TILE_B + SWZ((uint32_t)((grow + r * 32) * 128 + gseg * 16)),
                     gB + (size_t)(r * 32) * KSPL + kn * 64);
            }
        }
        CP_COMMIT();

        // compute from stage kc%STAGES
        const uint32_t sA = sb + (kc % STAGES) * STG_B;
        const uint32_t sB = sA + TILE_B;
        #pragma unroll
        for (int ks = 0; ks < 4; ++ks) {
            uint32_t a[4][4], bb[2][4];
            const uint32_t kb = ks * 32 + (lane >> 4) * 16;   // byte col
            #pragma unroll
            for (int mt = 0; mt < 4; ++mt) {
                uint32_t addr = sA + SWZ((uint32_t)((wm * 64 + mt * 16 + (lane & 15)) * 128) + kb);
                LDSM4(a[mt][0], a[mt][1], a[mt][2], a[mt][3], addr);
            }
            #pragma unroll
            for (int nt2 = 0; nt2 < 2; ++nt2) {
                uint32_t addr = sB + SWZ((uint32_t)((wn * 32 + nt2 * 16 + (lane & 15)) * 128) + kb);
                LDSM4(bb[nt2][0], bb[nt2][1], bb[nt2][2], bb[nt2][3], addr);
            }
            #pragma unroll
            for (int mt = 0; mt < 4; ++mt) {
                #pragma unroll
                for (int nt = 0; nt < 4; ++nt) {
                    uint32_t bfrag[2] = { bb[nt >> 1][nt & 1], bb[nt >> 1][(nt & 1) + 2] };
                    MMA16816(acc[mt][nt], a[mt], bfrag);
                }
            }
        }
    }

    // ---- epilogue: + bias2, write C ---------------------------------------
    const int group = lane >> 2;
    const int t4    = lane & 3;
    #pragma unroll
    for (int mt = 0; mt < 4; ++mt) {
        #pragma unroll
        for (int half = 0; half < 2; ++half) {
            const int row = m0 + wm * 64 + mt * 16 + group + half * 8;
            const float* b2 = g_bias2 + (size_t)(row & (MB_ - 1)) * D_;
            float* cp = C + (size_t)row * D_;
            #pragma unroll
            for (int nt = 0; nt < 4; ++nt) {
                const int col = n0 + wn * 32 + nt * 8 + t4 * 2;
                float2 bv = *reinterpret_cast<const float2*>(b2 + col);
                float2 v;
                v.x = acc[mt][nt][half * 2]     + bv.x;
                v.y = acc[mt][nt][half * 2 + 1] + bv.y;
                *reinterpret_cast<float2*>(cp + col) = v;
            }
        }
    }
}

// ---------------------------------------------------------------------------
extern "C" void kernel_launch(void* const* d_in, const int* in_sizes, int n_in,
                              void* d_out, int out_size) {
    const float* beat = (const float*)d_in[0];   // [8, 8192, 1024]
    const float* W    = (const float*)d_in[1];   // [1024, 1056]
    const float* bias = (const float*)d_in[2];   // [1024]
    float* out = (float*)d_out;                  // [8, 2048, 1024]

    cudaFuncSetAttribute(gemm_kernel, cudaFuncAttributeMaxDynamicSharedMemorySize,
                         SMEM_TOTAL);

    pool_split_kernel<<<ROWS, 256>>>((const float4*)beat);
    wsplit_kernel<<<D_, 256>>>(W);
    bias2_kernel<<<MB_, 256>>>(W, bias);
    dim3 grid(D_ / BN, ROWS / BM);               // (8, 128)
    gemm_kernel<<<grid, 256, SMEM_TOTAL>>>(out);
}

// round 5
// speedup vs baseline: 2.5660x; 1.3437x over previous
#include <cuda_runtime.h>
#include <cuda_bf16.h>
#include <cstdint>

// ---------------------------------------------------------------------------
// Shapes (fixed by the problem instance)
#define B_   8
#define M_   8192
#define D_   1024
#define MB_  2048
#define POS  32
#define KIN  1056
#define ROWS 16384          // B_*MB_
#define KA_  2048           // A' cols: [hi | lo]   (hi reused for chunks 32..47)
#define KW_  3072           // W' cols: [hi | hi | lo]

// Scratch (device globals; no allocation allowed)
__device__ __align__(256) __nv_bfloat16 g_A [(size_t)ROWS * KA_]; // ~67 MB
__device__ __align__(256) __nv_bfloat16 g_Ws[(size_t)D_   * KW_]; //  ~6.3 MB
__device__ __align__(256) float         g_Wt[POS * D_];           //  128 KB (W tail, transposed)
__device__ __align__(256) float         g_bias2[MB_ * D_];        //  ~8.4 MB

// ---------------------------------------------------------------------------
// PTX helpers (baseline sm_80/sm_90 features only — compute_103-safe)
// ---------------------------------------------------------------------------
__device__ __forceinline__ uint32_t smem_u32(const void* p) {
    uint32_t a;
    asm("{ .reg .u64 t; cvta.to.shared.u64 t, %1; cvt.u32.u64 %0, t; }" : "=r"(a) : "l"(p));
    return a;
}
#define CP16(dst, src) \
    asm volatile("cp.async.cg.shared.global [%0], [%1], 16;" :: "r"(dst), "l"(src) : "memory")
// NOTE: .noinc — barrier count already covers the producer threads.
#define CP_MBAR_ARRIVE_NOINC(a) \
    asm volatile("cp.async.mbarrier.arrive.noinc.shared::cta.b64 [%0];" :: "r"(a) : "memory")
#define MBAR_INIT(a, cnt) \
    asm volatile("mbarrier.init.shared.b64 [%0], %1;" :: "r"(a), "r"(cnt) : "memory")
#define MBAR_ARRIVE(a) \
    asm volatile("mbarrier.arrive.shared::cta.b64 _, [%0];" :: "r"(a) : "memory")
#define MBAR_WAIT(a, ph) do {                                                   \
    uint32_t _m = (a), _p = (ph), _d;                                           \
    asm volatile("{ .reg .pred p; mbarrier.try_wait.parity.acquire.cta.shared::cta.b64 p, [%1], %2; selp.b32 %0,1,0,p; }" \
        : "=r"(_d) : "r"(_m), "r"(_p) : "memory");                              \
    if (!_d) {                                                                  \
        asm volatile("{ .reg .pred P1; WL_%=: mbarrier.try_wait.parity.acquire.cta.shared::cta.b64 P1, [%0], %1, 0x989680; @P1 bra.uni WD_%=; bra.uni WL_%=; WD_%=: }" \
            :: "r"(_m), "r"(_p) : "memory");                                    \
    } } while (0)
#define LDSM4(r0, r1, r2, r3, a) \
    asm volatile("ldmatrix.sync.aligned.m8n8.x4.shared.b16 {%0,%1,%2,%3}, [%4];" \
        : "=r"(r0), "=r"(r1), "=r"(r2), "=r"(r3) : "r"(a))
#define MMA16816(d, a, b) \
    asm volatile("mma.sync.aligned.m16n8k16.row.col.f32.bf16.bf16.f32 " \
        "{%0,%1,%2,%3}, {%4,%5,%6,%7}, {%8,%9}, {%0,%1,%2,%3};" \
        : "+f"((d)[0]), "+f"((d)[1]), "+f"((d)[2]), "+f"((d)[3]) \
        : "r"((a)[0]), "r"((a)[1]), "r"((a)[2]), "r"((a)[3]), "r"((b)[0]), "r"((b)[1]))

#define SWZ(x) ((x) ^ (((x) >> 3) & 0x70))

__device__ __forceinline__ void bf16_split(float x, unsigned short& h, unsigned short& l) {
    __nv_bfloat16 hb = __float2bfloat16(x);
    __nv_bfloat16 lb = __float2bfloat16(x - __bfloat162float(hb));
    h = __bfloat16_as_ushort(hb);
    l = __bfloat16_as_ushort(lb);
}

// ---------------------------------------------------------------------------
// Kernel 1: 4-row mean pool + bf16 hi/lo split.  A' = [hi | lo], K=2048
// ---------------------------------------------------------------------------
__global__ __launch_bounds__(256) void pool_split_kernel(const float4* __restrict__ in) {
    size_t i = (size_t)blockIdx.x * 256 + threadIdx.x;   // one float4 of one out row
    int row = (int)(i >> 8);
    int c4  = (int)(i & 255);
    const float4* p = in + ((size_t)row * 4) * 256 + c4;
    float4 a = p[0], b = p[256], d = p[512], e = p[768];
    float m0 = 0.25f * (a.x + b.x + d.x + e.x);
    float m1 = 0.25f * (a.y + b.y + d.y + e.y);
    float m2 = 0.25f * (a.z + b.z + d.z + e.z);
    float m3 = 0.25f * (a.w + b.w + d.w + e.w);
    unsigned short h0, h1, h2, h3, l0, l1, l2, l3;
    bf16_split(m0, h0, l0); bf16_split(m1, h1, l1);
    bf16_split(m2, h2, l2); bf16_split(m3, h3, l3);
    uint2 hp, lp;
    hp.x = (uint32_t)h0 | ((uint32_t)h1 << 16);  hp.y = (uint32_t)h2 | ((uint32_t)h3 << 16);
    lp.x = (uint32_t)l0 | ((uint32_t)l1 << 16);  lp.y = (uint32_t)l2 | ((uint32_t)l3 << 16);
    __nv_bfloat16* base = g_A + (size_t)row * KA_ + c4 * 4;
    *reinterpret_cast<uint2*>(base)        = hp;   // block 0: hi
    *reinterpret_cast<uint2*>(base + 1024) = lp;   // block 1: lo
}

// ---------------------------------------------------------------------------
// Kernel 2: W split.  W' = [hi | hi | lo]  (A_hi*W_hi + A_lo*W_hi + A_hi*W_lo)
// ---------------------------------------------------------------------------
__global__ __launch_bounds__(256) void wsplit_kernel(const float* __restrict__ W) {
    int i  = blockIdx.x * 256 + threadIdx.x;   // over 1024 * 256
    int o  = i >> 8;
    int c4 = i & 255;
    float4 w = *reinterpret_cast<const float4*>(W + (size_t)o * KIN + c4 * 4);
    unsigned short h0, h1, h2, h3, l0, l1, l2, l3;
    bf16_split(w.x, h0, l0); bf16_split(w.y, h1, l1);
    bf16_split(w.z, h2, l2); bf16_split(w.w, h3, l3);
    uint2 hp, lp;
    hp.x = (uint32_t)h0 | ((uint32_t)h1 << 16);  hp.y = (uint32_t)h2 | ((uint32_t)h3 << 16);
    lp.x = (uint32_t)l0 | ((uint32_t)l1 << 16);  lp.y = (uint32_t)l2 | ((uint32_t)l3 << 16);
    __nv_bfloat16* base = g_Ws + (size_t)o * KW_ + c4 * 4;
    *reinterpret_cast<uint2*>(base)        = hp;
    *reinterpret_cast<uint2*>(base + 1024) = hp;
    *reinterpret_cast<uint2*>(base + 2048) = lp;
}

// ---------------------------------------------------------------------------
// Kernel 2b: transpose W tail -> Wt[j][o]  (coalesced source for bias2)
// ---------------------------------------------------------------------------
__global__ void wtail_kernel(const float* __restrict__ W) {
    int o = threadIdx.x;                  // 1024 threads, 1 block
    const float* src = W + (size_t)o * KIN + D_;
    #pragma unroll
    for (int j = 0; j < POS; ++j)
        g_Wt[j * D_ + o] = src[j];
}

// ---------------------------------------------------------------------------
// Kernel 3: fourier bias, coalesced: bias2[mb,o] = b[o] + sum_j ff(mb,j)*Wt[j,o]
// 256 blocks x 256 threads; each block: 8 mb rows, each thread: 4 o columns.
// ---------------------------------------------------------------------------
__global__ __launch_bounds__(256) void bias2_kernel(const float* __restrict__ bias) {
    __shared__ float ff[8][POS];
    const int tid = threadIdx.x;
    const int blk = blockIdx.x;
    if (tid < 128) {
        int r = tid >> 4, f = tid & 15;
        int mb = blk * 8 + r;
        float pos  = (float)mb / (float)(MB_ - 1);
        float freq = expf((float)f * (6.907755278982137f / 15.0f));
        float ang  = pos * freq;
        ff[r][f]      = sinf(ang);
        ff[r][f + 16] = cosf(ang);
    }
    __syncthreads();
    float acc[8][4];
    #pragma unroll
    for (int r = 0; r < 8; ++r)
        #pragma unroll
        for (int k = 0; k < 4; ++k) acc[r][k] = bias[tid + k * 256];
    #pragma unroll
    for (int j = 0; j < POS; ++j) {
        float w[4];
        #pragma unroll
        for (int k = 0; k < 4; ++k) w[k] = g_Wt[j * D_ + tid + k * 256];
        #pragma unroll
        for (int r = 0; r < 8; ++r) {
            float f = ff[r][j];
            #pragma unroll
            for (int k = 0; k < 4; ++k) acc[r][k] += f * w[k];
        }
    }
    #pragma unroll
    for (int r = 0; r < 8; ++r)
        #pragma unroll
        for (int k = 0; k < 4; ++k)
            g_bias2[(size_t)(blk * 8 + r) * D_ + tid + k * 256] = acc[r][k];
}

// ---------------------------------------------------------------------------
// Kernel 4: warp-specialized bf16 mma.sync GEMM.
// C[16384,1024] = A'[.,K=3072 via remap] @ W'[1024,3072]^T  (+ bias2)
// 128x128x64 tiles, 3-stage cp.async pipeline with mbarriers.
// 384 threads: warps 0-7 consumers (64x32 warp tiles), warps 8-11 producers.
// ---------------------------------------------------------------------------
#define BM 128
#define BN 128
#define BK 64
#define NKC 48               // total K chunks (3 * 1024 / 64)
#define STAGES 3
#define TILE_B (BM * BK * 2) // 16 KB (A or B half)
#define STG_B  (2 * TILE_B)  // 32 KB per stage
#define BAR_OFF (STAGES * STG_B)
#define SMEM_TOTAL (BAR_OFF + 128)
#define FULL_BAR(s)  (BAR_OFF + (s) * 16)
#define EMPTY_BAR(s) (BAR_OFF + (s) * 16 + 8)

extern __shared__ char dynsmem[];

__global__ __launch_bounds__(384, 1) void gemm_kernel(float* __restrict__ C) {
    const uint32_t sb = smem_u32(dynsmem);
    const int tid  = threadIdx.x;
    const int lane = tid & 31;
    const int m0 = blockIdx.y * BM;
    const int n0 = blockIdx.x * BN;

    if (tid == 0) {
        #pragma unroll
        for (int s = 0; s < STAGES; ++s) {
            MBAR_INIT(sb + FULL_BAR(s), 128);   // 128 producer threads (noinc arrive)
            MBAR_INIT(sb + EMPTY_BAR(s), 256);  // 256 consumer threads arrive
        }
    }
    __syncthreads();

    if (tid >= 256) {
        // ---------------- producers: 128 threads, cp.async ------------------
        const int pt = tid - 256;           // 0..127
        int phase = 1;                      // first empty-wait passes immediately
        for (int kc = 0; kc < NKC; ++kc) {
            const int s = kc % STAGES;
            MBAR_WAIT(sb + EMPTY_BAR(s), phase);
            const int kA = (kc < 32) ? kc : kc - 32;   // hi-block reuse
            const uint32_t sA = sb + s * STG_B;
            #pragma unroll
            for (int i = 0; i < 8; ++i) {
                int id = pt + (i << 7);
                int row = id >> 3, seg = id & 7;
                uint32_t off = SWZ((uint32_t)(row * 128 + seg * 16));
                CP16(sA + off,
                     g_A + (size_t)(m0 + row) * KA_ + kA * 64 + seg * 8);
                CP16(sA + TILE_B + off,
                     g_Ws + (size_t)(n0 + row) * KW_ + kc * 64 + seg * 8);
            }
            CP_MBAR_ARRIVE_NOINC(sb + FULL_BAR(s));
            if (s == STAGES - 1) phase ^= 1;
        }
        return;
    }

    // -------------------- consumers: 8 warps, mma --------------------------
    const int wid = tid >> 5;
    const int wm  = wid >> 2;              // 0..1  (M dir, 64 rows)
    const int wn  = wid & 3;               // 0..3  (N dir, 32 cols)

    float acc[4][4][4];
    #pragma unroll
    for (int i = 0; i < 4; ++i)
        #pragma unroll
        for (int j = 0; j < 4; ++j)
            #pragma unroll
            for (int v = 0; v < 4; ++v) acc[i][j][v] = 0.0f;

    int phase = 0;
    for (int kc = 0; kc < NKC; ++kc) {
        const int s = kc % STAGES;
        MBAR_WAIT(sb + FULL_BAR(s), phase);
        const uint32_t sA = sb + s * STG_B;
        const uint32_t sB = sA + TILE_B;
        #pragma unroll
        for (int ks = 0; ks < 4; ++ks) {
            uint32_t a[4][4], bb[2][4];
            const uint32_t kb = ks * 32 + (lane >> 4) * 16;   // byte col
            #pragma unroll
            for (int mt = 0; mt < 4; ++mt) {
                uint32_t addr = sA + SWZ((uint32_t)((wm * 64 + mt * 16 + (lane & 15)) * 128) + kb);
                LDSM4(a[mt][0], a[mt][1], a[mt][2], a[mt][3], addr);
            }
            #pragma unroll
            for (int nt2 = 0; nt2 < 2; ++nt2) {
                uint32_t addr = sB + SWZ((uint32_t)((wn * 32 + nt2 * 16 + (lane & 15)) * 128) + kb);
                LDSM4(bb[nt2][0], bb[nt2][1], bb[nt2][2], bb[nt2][3], addr);
            }
            #pragma unroll
            for (int mt = 0; mt < 4; ++mt) {
                #pragma unroll
                for (int nt = 0; nt < 4; ++nt) {
                    uint32_t bfrag[2] = { bb[nt >> 1][nt & 1], bb[nt >> 1][(nt & 1) + 2] };
                    MMA16816(acc[mt][nt], a[mt], bfrag);
                }
            }
        }
        MBAR_ARRIVE(sb + EMPTY_BAR(s));
        if (s == STAGES - 1) phase ^= 1;
    }

    // ---- epilogue: + bias2, write C ---------------------------------------
    const int group = lane >> 2;
    const int t4    = lane & 3;
    #pragma unroll
    for (int mt = 0; mt < 4; ++mt) {
        #pragma unroll
        for (int half = 0; half < 2; ++half) {
            const int row = m0 + wm * 64 + mt * 16 + group + half * 8;
            const float* b2 = g_bias2 + (size_t)(row & (MB_ - 1)) * D_;
            float* cp = C + (size_t)row * D_;
            #pragma unroll
            for (int nt = 0; nt < 4; ++nt) {
                const int col = n0 + wn * 32 + nt * 8 + t4 * 2;
                float2 bv = *reinterpret_cast<const float2*>(b2 + col);
                float2 v;
                v.x = acc[mt][nt][half * 2]     + bv.x;
                v.y = acc[mt][nt][half * 2 + 1] + bv.y;
                *reinterpret_cast<float2*>(cp + col) = v;
            }
        }
    }
}

// ---------------------------------------------------------------------------
extern "C" void kernel_launch(void* const* d_in, const int* in_sizes, int n_in,
                              void* d_out, int out_size) {
    const float* beat = (const float*)d_in[0];   // [8, 8192, 1024]
    const float* W    = (const float*)d_in[1];   // [1024, 1056]
    const float* bias = (const float*)d_in[2];   // [1024]
    float* out = (float*)d_out;                  // [8, 2048, 1024]

    cudaFuncSetAttribute(gemm_kernel, cudaFuncAttributeMaxDynamicSharedMemorySize,
                         SMEM_TOTAL);

    pool_split_kernel<<<ROWS, 256>>>((const float4*)beat);
    wsplit_kernel<<<D_, 256>>>(W);
    wtail_kernel<<<1, 1024>>>(W);
    bias2_kernel<<<MB_ / 8, 256>>>(bias);
    dim3 grid(D_ / BN, ROWS / BM);               // (8, 128)
    gemm_kernel<<<grid, 384, SMEM_TOTAL>>>(out);
}

// round 6
// speedup vs baseline: 5.6704x; 2.2098x over previous
#include <cuda_runtime.h>
#include <cuda_fp16.h>
#include <cstdint>

// ---------------------------------------------------------------------------
// Shapes (fixed by the problem instance)
#define B_   8
#define M_   8192
#define D_   1024
#define MB_  2048
#define POS  32
#define KIN  1056
#define ROWS 16384          // B_*MB_

// Scratch (device globals; no allocation allowed)
__device__ __align__(256) __half g_A [(size_t)ROWS * D_];  // ~33.5 MB fp16
__device__ __align__(256) __half g_Ws[(size_t)D_   * D_];  //  2 MB fp16
__device__ __align__(256) float  g_Wt[POS * D_];           //  128 KB (W tail, transposed)
__device__ __align__(256) float  g_bias2[MB_ * D_];        //  ~8.4 MB

// ---------------------------------------------------------------------------
// PTX helpers (baseline sm_80 features only — compute_103-safe)
// ---------------------------------------------------------------------------
__device__ __forceinline__ uint32_t smem_u32(const void* p) {
    uint32_t a;
    asm("{ .reg .u64 t; cvta.to.shared.u64 t, %1; cvt.u32.u64 %0, t; }" : "=r"(a) : "l"(p));
    return a;
}
#define CP16(dst, src) \
    asm volatile("cp.async.cg.shared.global [%0], [%1], 16;" :: "r"(dst), "l"(src) : "memory")
#define CP_COMMIT() asm volatile("cp.async.commit_group;" ::: "memory")
#define CP_WAIT(n)  asm volatile("cp.async.wait_group %0;" :: "n"(n) : "memory")
#define LDSM4(r0, r1, r2, r3, a) \
    asm volatile("ldmatrix.sync.aligned.m8n8.x4.shared.b16 {%0,%1,%2,%3}, [%4];" \
        : "=r"(r0), "=r"(r1), "=r"(r2), "=r"(r3) : "r"(a))
#define MMA16816(d, a, b) \
    asm volatile("mma.sync.aligned.m16n8k16.row.col.f32.f16.f16.f32 " \
        "{%0,%1,%2,%3}, {%4,%5,%6,%7}, {%8,%9}, {%0,%1,%2,%3};" \
        : "+f"((d)[0]), "+f"((d)[1]), "+f"((d)[2]), "+f"((d)[3]) \
        : "r"((a)[0]), "r"((a)[1]), "r"((a)[2]), "r"((a)[3]), "r"((b)[0]), "r"((b)[1]))

#define SWZ(x) ((x) ^ (((x) >> 3) & 0x70))

// ---------------------------------------------------------------------------
// Kernel 1: 4-row mean pool -> fp16.
// ---------------------------------------------------------------------------
__global__ __launch_bounds__(256) void pool_kernel(const float4* __restrict__ in) {
    size_t i = (size_t)blockIdx.x * 256 + threadIdx.x;   // one float4 of one out row
    int row = (int)(i >> 8);
    int c4  = (int)(i & 255);
    const float4* p = in + ((size_t)row * 4) * 256 + c4;
    float4 a = p[0], b = p[256], d = p[512], e = p[768];
    __half h0 = __float2half(0.25f * (a.x + b.x + d.x + e.x));
    __half h1 = __float2half(0.25f * (a.y + b.y + d.y + e.y));
    __half h2 = __float2half(0.25f * (a.z + b.z + d.z + e.z));
    __half h3 = __float2half(0.25f * (a.w + b.w + d.w + e.w));
    uint2 v;
    v.x = (uint32_t)__half_as_ushort(h0) | ((uint32_t)__half_as_ushort(h1) << 16);
    v.y = (uint32_t)__half_as_ushort(h2) | ((uint32_t)__half_as_ushort(h3) << 16);
    *reinterpret_cast<uint2*>(g_A + (size_t)row * D_ + c4 * 4) = v;
}

// ---------------------------------------------------------------------------
// Kernel 2: W head -> fp16 (first 1024 cols of each row).
// ---------------------------------------------------------------------------
__global__ __launch_bounds__(256) void wsplit_kernel(const float* __restrict__ W) {
    int i  = blockIdx.x * 256 + threadIdx.x;   // over 1024 * 256
    int o  = i >> 8;
    int c4 = i & 255;
    float4 w = *reinterpret_cast<const float4*>(W + (size_t)o * KIN + c4 * 4);
    __half h0 = __float2half(w.x), h1 = __float2half(w.y);
    __half h2 = __float2half(w.z), h3 = __float2half(w.w);
    uint2 v;
    v.x = (uint32_t)__half_as_ushort(h0) | ((uint32_t)__half_as_ushort(h1) << 16);
    v.y = (uint32_t)__half_as_ushort(h2) | ((uint32_t)__half_as_ushort(h3) << 16);
    *reinterpret_cast<uint2*>(g_Ws + (size_t)o * D_ + c4 * 4) = v;
}

// ---------------------------------------------------------------------------
// Kernel 2b: transpose W tail -> Wt[j][o]  (coalesced source for bias2)
// ---------------------------------------------------------------------------
__global__ void wtail_kernel(const float* __restrict__ W) {
    int o = threadIdx.x;                  // 1024 threads, 1 block
    const float* src = W + (size_t)o * KIN + D_;
    #pragma unroll
    for (int j = 0; j < POS; ++j)
        g_Wt[j * D_ + o] = src[j];
}

// ---------------------------------------------------------------------------
// Kernel 3: fourier bias, coalesced (fp32 exact).
// ---------------------------------------------------------------------------
__global__ __launch_bounds__(256) void bias2_kernel(const float* __restrict__ bias) {
    __shared__ float ff[8][POS];
    const int tid = threadIdx.x;
    const int blk = blockIdx.x;
    if (tid < 128) {
        int r = tid >> 4, f = tid & 15;
        int mb = blk * 8 + r;
        float pos  = (float)mb / (float)(MB_ - 1);
        float freq = expf((float)f * (6.907755278982137f / 15.0f));
        float ang  = pos * freq;
        ff[r][f]      = sinf(ang);
        ff[r][f + 16] = cosf(ang);
    }
    __syncthreads();
    float acc[8][4];
    #pragma unroll
    for (int r = 0; r < 8; ++r)
        #pragma unroll
        for (int k = 0; k < 4; ++k) acc[r][k] = bias[tid + k * 256];
    #pragma unroll
    for (int j = 0; j < POS; ++j) {
        float w[4];
        #pragma unroll
        for (int k = 0; k < 4; ++k) w[k] = g_Wt[j * D_ + tid + k * 256];
        #pragma unroll
        for (int r = 0; r < 8; ++r) {
            float f = ff[r][j];
            #pragma unroll
            for (int k = 0; k < 4; ++k) acc[r][k] += f * w[k];
        }
    }
    #pragma unroll
    for (int r = 0; r < 8; ++r)
        #pragma unroll
        for (int k = 0; k < 4; ++k)
            g_bias2[(size_t)(blk * 8 + r) * D_ + tid + k * 256] = acc[r][k];
}

// ---------------------------------------------------------------------------
// Kernel 4: fp16 mma.sync GEMM.  C[16384,1024] = A[.,1024] @ W[1024,1024]^T
// 128x128x64 tiles, 3-stage cp.async, SW128 smem, ldmatrix, 8 warps (2x4),
// warp tile 64x32, fp32 accumulators, fused bias2 epilogue.
// ---------------------------------------------------------------------------
#define BM 128
#define BN 128
#define BK 64
#define NKC 16               // 1024 / 64
#define STAGES 3
#define TILE_B (BM * BK * 2) // 16 KB (A or B half)
#define STG_B  (2 * TILE_B)  // 32 KB per stage
#define SMEM_TOTAL (STAGES * STG_B)  // 96 KB

extern __shared__ char dynsmem[];

__global__ __launch_bounds__(256, 1) void gemm_kernel(float* __restrict__ C) {
    const uint32_t sb = smem_u32(dynsmem);
    const int tid  = threadIdx.x;
    const int lane = tid & 31;
    const int wid  = tid >> 5;
    const int wm   = wid >> 2;          // 0..1  (M dir, 64 rows)
    const int wn   = wid & 3;           // 0..3  (N dir, 32 cols)
    const int m0 = blockIdx.y * BM;
    const int n0 = blockIdx.x * BN;

    const int grow = tid >> 3;          // 0..31 base row (stride 32)
    const int gseg = tid & 7;           // 16B segment within 128B row
    const __half* gA = g_A  + (size_t)(m0 + grow) * D_ + gseg * 8;
    const __half* gB = g_Ws + (size_t)(n0 + grow) * D_ + gseg * 8;

    float acc[4][4][4];
    #pragma unroll
    for (int i = 0; i < 4; ++i)
        #pragma unroll
        for (int j = 0; j < 4; ++j)
            #pragma unroll
            for (int v = 0; v < 4; ++v) acc[i][j][v] = 0.0f;

    // ---- prologue: prefetch STAGES-1 tiles --------------------------------
    #pragma unroll
    for (int s = 0; s < STAGES - 1; ++s) {
        const uint32_t sa = sb + s * STG_B;
        #pragma unroll
        for (int r = 0; r < 4; ++r) {
            uint32_t off = SWZ((uint32_t)((grow + r * 32) * 128 + gseg * 16));
            CP16(sa + off,          gA + (size_t)(r * 32) * D_ + s * 64);
            CP16(sa + TILE_B + off, gB + (size_t)(r * 32) * D_ + s * 64);
        }
        CP_COMMIT();
    }

    // ---- mainloop ---------------------------------------------------------
    for (int kc = 0; kc < NKC; ++kc) {
        CP_WAIT(STAGES - 2);
        __syncthreads();

        const int kn = kc + STAGES - 1;
        if (kn < NKC) {
            const uint32_t sa = sb + (kn % STAGES) * STG_B;
            #pragma unroll
            for (int r = 0; r < 4; ++r) {
                uint32_t off = SWZ((uint32_t)((grow + r * 32) * 128 + gseg * 16));
                CP16(sa + off,          gA + (size_t)(r * 32) * D_ + kn * 64);
                CP16(sa + TILE_B + off, gB + (size_t)(r * 32) * D_ + kn * 64);
            }
        }
        CP_COMMIT();

        const uint32_t sA = sb + (kc % STAGES) * STG_B;
        const uint32_t sB = sA + TILE_B;
        #pragma unroll
        for (int ks = 0; ks < 4; ++ks) {
            uint32_t a[4][4], bb[2][4];
            const uint32_t kb = ks * 32 + (lane >> 4) * 16;   // byte col
            #pragma unroll
            for (int mt = 0; mt < 4; ++mt) {
                uint32_t addr = sA + SWZ((uint32_t)((wm * 64 + mt * 16 + (lane & 15)) * 128) + kb);
                LDSM4(a[mt][0], a[mt][1], a[mt][2], a[mt][3], addr);
            }
            #pragma unroll
            for (int nt2 = 0; nt2 < 2; ++nt2) {
                uint32_t addr = sB + SWZ((uint32_t)((wn * 32 + nt2 * 16 + (lane & 15)) * 128) + kb);
                LDSM4(bb[nt2][0], bb[nt2][1], bb[nt2][2], bb[nt2][3], addr);
            }
            #pragma unroll
            for (int mt = 0; mt < 4; ++mt) {
                #pragma unroll
                for (int nt = 0; nt < 4; ++nt) {
                    uint32_t bfrag[2] = { bb[nt >> 1][nt & 1], bb[nt >> 1][(nt & 1) + 2] };
                    MMA16816(acc[mt][nt], a[mt], bfrag);
                }
            }
        }
    }

    // ---- epilogue: + bias2, write C ---------------------------------------
    const int group = lane >> 2;
    const int t4    = lane & 3;
    #pragma unroll
    for (int mt = 0; mt < 4; ++mt) {
        #pragma unroll
        for (int half = 0; half < 2; ++half) {
            const int row = m0 + wm * 64 + mt * 16 + group + half * 8;
            const float* b2 = g_bias2 + (size_t)(row & (MB_ - 1)) * D_;
            float* cp = C + (size_t)row * D_;
            #pragma unroll
            for (int nt = 0; nt < 4; ++nt) {
                const int col = n0 + wn * 32 + nt * 8 + t4 * 2;
                float2 bv = *reinterpret_cast<const float2*>(b2 + col);
                float2 v;
                v.x = acc[mt][nt][half * 2]     + bv.x;
                v.y = acc[mt][nt][half * 2 + 1] + bv.y;
                *reinterpret_cast<float2*>(cp + col) = v;
            }
        }
    }
}

// ---------------------------------------------------------------------------
extern "C" void kernel_launch(void* const* d_in, const int* in_sizes, int n_in,
                              void* d_out, int out_size) {
    const float* beat = (const float*)d_in[0];   // [8, 8192, 1024]
    const float* W    = (const float*)d_in[1];   // [1024, 1056]
    const float* bias = (const float*)d_in[2];   // [1024]
    float* out = (float*)d_out;                  // [8, 2048, 1024]

    cudaFuncSetAttribute(gemm_kernel, cudaFuncAttributeMaxDynamicSharedMemorySize,
                         SMEM_TOTAL);

    pool_kernel<<<ROWS, 256>>>((const float4*)beat);
    wsplit_kernel<<<D_, 256>>>(W);
    wtail_kernel<<<1, 1024>>>(W);
    bias2_kernel<<<MB_ / 8, 256>>>(bias);
    dim3 grid(D_ / BN, ROWS / BM);               // (8, 128)
    gemm_kernel<<<grid, 256, SMEM_TOTAL>>>(out);
}

// round 8
// speedup vs baseline: 6.6709x; 1.1765x over previous
#include <cuda_runtime.h>
#include <cuda_fp16.h>
#include <cstdint>

// ---------------------------------------------------------------------------
// Shapes (fixed by the problem instance)
#define B_   8
#define M_   8192
#define D_   1024
#define MB_  2048
#define POS  32
#define KIN  1056
#define ROWS 16384          // B_*MB_
#define KP   1088           // padded GEMM K: 1024 head + 32 ff + 32 zero

// Scratch (device globals; no allocation allowed)
__device__ __align__(256) __half g_A [(size_t)ROWS * KP];  // ~35.7 MB fp16
__device__ __align__(256) __half g_Ws[(size_t)D_   * KP];  //  ~2.2 MB fp16

// ---------------------------------------------------------------------------
// PTX helpers (baseline sm_80 features only — compute_103-safe)
// ---------------------------------------------------------------------------
__device__ __forceinline__ uint32_t smem_u32(const void* p) {
    uint32_t a;
    asm("{ .reg .u64 t; cvta.to.shared.u64 t, %1; cvt.u32.u64 %0, t; }" : "=r"(a) : "l"(p));
    return a;
}
#define CP16(dst, src) \
    asm volatile("cp.async.cg.shared.global [%0], [%1], 16;" :: "r"(dst), "l"(src) : "memory")
#define CP_COMMIT() asm volatile("cp.async.commit_group;" ::: "memory")
#define CP_WAIT(n)  asm volatile("cp.async.wait_group %0;" :: "n"(n) : "memory")
#define LDSM4(r0, r1, r2, r3, a) \
    asm volatile("ldmatrix.sync.aligned.m8n8.x4.shared.b16 {%0,%1,%2,%3}, [%4];" \
        : "=r"(r0), "=r"(r1), "=r"(r2), "=r"(r3) : "r"(a))
#define MMA16816(d, a, b) \
    asm volatile("mma.sync.aligned.m16n8k16.row.col.f32.f16.f16.f32 " \
        "{%0,%1,%2,%3}, {%4,%5,%6,%7}, {%8,%9}, {%0,%1,%2,%3};" \
        : "+f"((d)[0]), "+f"((d)[1]), "+f"((d)[2]), "+f"((d)[3]) \
        : "r"((a)[0]), "r"((a)[1]), "r"((a)[2]), "r"((a)[3]), "r"((b)[0]), "r"((b)[1]))

#define SWZ(x) ((x) ^ (((x) >> 3) & 0x70))

__device__ __forceinline__ uint32_t pack2(float a, float b) {
    return (uint32_t)__half_as_ushort(__float2half(a)) |
           ((uint32_t)__half_as_ushort(__float2half(b)) << 16);
}

// ---------------------------------------------------------------------------
// Kernel 1: 4-row mean pool -> fp16 head columns (0..1023), row stride KP.
// ---------------------------------------------------------------------------
__global__ __launch_bounds__(256) void pool_kernel(const float4* __restrict__ in) {
    size_t i = (size_t)blockIdx.x * 256 + threadIdx.x;
    int row = (int)(i >> 8);
    int c4  = (int)(i & 255);
    const float4* p = in + ((size_t)row * 4) * 256 + c4;
    float4 a = p[0], b = p[256], d = p[512], e = p[768];
    uint2 v;
    v.x = pack2(0.25f * (a.x + b.x + d.x + e.x), 0.25f * (a.y + b.y + d.y + e.y));
    v.y = pack2(0.25f * (a.z + b.z + d.z + e.z), 0.25f * (a.w + b.w + d.w + e.w));
    *reinterpret_cast<uint2*>(g_A + (size_t)row * KP + c4 * 4) = v;
}

// ---------------------------------------------------------------------------
// Kernel 1b: fill A tail cols 1024..1087 with [ff(mb) | zeros] for all batches.
// grid = MB_, 64 threads.
// ---------------------------------------------------------------------------
__global__ void ff_fill_kernel() {
    int mb = blockIdx.x;
    int j  = threadIdx.x;            // 0..63
    __half h;
    if (j < 32) {
        float pos  = (float)mb / (float)(MB_ - 1);
        int   f    = j & 15;
        float freq = expf((float)f * (6.907755278982137f / 15.0f));
        float ang  = pos * freq;
        h = __float2half((j < 16) ? sinf(ang) : cosf(ang));
    } else {
        h = __float2half(0.0f);      // zero pad cols 1056..1087
    }
    #pragma unroll
    for (int b = 0; b < B_; ++b)
        g_A[(size_t)(b * MB_ + mb) * KP + 1024 + j] = h;
}

// ---------------------------------------------------------------------------
// Kernel 2: W -> fp16, cols 0..1055 from W, 1056..1087 zero.  grid = D_.
// (Round-7 bug fix: pack into uint4, NOT ushort4 — fields must hold 2 halves.)
// ---------------------------------------------------------------------------
__global__ __launch_bounds__(160) void wsplit_kernel(const float* __restrict__ W) {
    int o = blockIdx.x;
    int t = threadIdx.x;             // 0..159, active t < 136
    if (t >= 136) return;
    uint4 v;
    if (t < 132) {
        const float* src = W + (size_t)o * KIN + t * 8;
        float4 w0 = *reinterpret_cast<const float4*>(src);
        float4 w1 = *reinterpret_cast<const float4*>(src + 4);
        v.x = pack2(w0.x, w0.y);
        v.y = pack2(w0.z, w0.w);
        v.z = pack2(w1.x, w1.y);
        v.w = pack2(w1.z, w1.w);
    } else {
        v.x = v.y = v.z = v.w = 0;
    }
    *reinterpret_cast<uint4*>(g_Ws + (size_t)o * KP + t * 8) = v;
}

// ---------------------------------------------------------------------------
// Kernel 3: fp16 mma.sync GEMM.  C[16384,1024] = A[.,1088] @ Ws[1024,1088]^T + b
// 128x128x64 tiles, 3-stage cp.async, SW128 smem, ldmatrix w/ fragment
// double-buffering, 8 warps (2x4), warp tile 64x32, fp32 accumulators.
// ---------------------------------------------------------------------------
#define BM 128
#define BN 128
#define BK 64
#define NKC 17               // 1088 / 64
#define STAGES 3
#define TILE_B (BM * BK * 2) // 16 KB (A or B half)
#define STG_B  (2 * TILE_B)  // 32 KB per stage
#define SMEM_TOTAL (STAGES * STG_B)  // 96 KB

extern __shared__ char dynsmem[];

__global__ __launch_bounds__(256, 1) void gemm_kernel(float* __restrict__ C,
                                                      const float* __restrict__ bias) {
    const uint32_t sb = smem_u32(dynsmem);
    const int tid  = threadIdx.x;
    const int lane = tid & 31;
    const int wid  = tid >> 5;
    const int wm   = wid >> 2;          // 0..1  (M dir, 64 rows)
    const int wn   = wid & 3;           // 0..3  (N dir, 32 cols)
    const int m0 = blockIdx.y * BM;
    const int n0 = blockIdx.x * BN;

    const int grow = tid >> 3;          // 0..31 base row (stride 32)
    const int gseg = tid & 7;           // 16B segment within 128B row
    const __half* gA = g_A  + (size_t)(m0 + grow) * KP + gseg * 8;
    const __half* gB = g_Ws + (size_t)(n0 + grow) * KP + gseg * 8;

    // hoisted ldmatrix address components: SWZ(row*128+kb) = row*128 + (kb ^ swz)
    uint32_t aBase[4], aSwz[4], bBase[2], bSwz[2];
    #pragma unroll
    for (int mt = 0; mt < 4; ++mt) {
        int r = wm * 64 + mt * 16 + (lane & 15);
        aBase[mt] = (uint32_t)(r * 128);
        aSwz[mt]  = (uint32_t)((r & 7) << 4);
    }
    #pragma unroll
    for (int nt2 = 0; nt2 < 2; ++nt2) {
        int r = wn * 32 + nt2 * 16 + (lane & 15);
        bBase[nt2] = (uint32_t)(r * 128);
        bSwz[nt2]  = (uint32_t)((r & 7) << 4);
    }
    const uint32_t hi16 = (lane >> 4) * 16;

    float acc[4][4][4];
    #pragma unroll
    for (int i = 0; i < 4; ++i)
        #pragma unroll
        for (int j = 0; j < 4; ++j)
            #pragma unroll
            for (int v = 0; v < 4; ++v) acc[i][j][v] = 0.0f;

    // ---- prologue: prefetch STAGES-1 tiles --------------------------------
    #pragma unroll
    for (int s = 0; s < STAGES - 1; ++s) {
        const uint32_t sa = sb + s * STG_B;
        #pragma unroll
        for (int r = 0; r < 4; ++r) {
            uint32_t off = SWZ((uint32_t)((grow + r * 32) * 128 + gseg * 16));
            CP16(sa + off,          gA + (size_t)(r * 32) * KP + s * 64);
            CP16(sa + TILE_B + off, gB + (size_t)(r * 32) * KP + s * 64);
        }
        CP_COMMIT();
    }

    uint32_t afr[2][4][4], bfr[2][2][4];

    // ---- mainloop ---------------------------------------------------------
    for (int kc = 0; kc < NKC; ++kc) {
        CP_WAIT(1);
        __syncthreads();

        const int kn = kc + STAGES - 1;
        if (kn < NKC) {
            const uint32_t sa = sb + (kn % STAGES) * STG_B;
            #pragma unroll
            for (int r = 0; r < 4; ++r) {
                uint32_t off = SWZ((uint32_t)((grow + r * 32) * 128 + gseg * 16));
                CP16(sa + off,          gA + (size_t)(r * 32) * KP + kn * 64);
                CP16(sa + TILE_B + off, gB + (size_t)(r * 32) * KP + kn * 64);
            }
        }
        CP_COMMIT();

        const uint32_t sA = sb + (kc % STAGES) * STG_B;
        const uint32_t sB = sA + TILE_B;

        // load ks=0 fragments
        {
            const uint32_t kb = hi16;
            #pragma unroll
            for (int mt = 0; mt < 4; ++mt)
                LDSM4(afr[0][mt][0], afr[0][mt][1], afr[0][mt][2], afr[0][mt][3],
                      sA + aBase[mt] + (kb ^ aSwz[mt]));
            #pragma unroll
            for (int nt2 = 0; nt2 < 2; ++nt2)
                LDSM4(bfr[0][nt2][0], bfr[0][nt2][1], bfr[0][nt2][2], bfr[0][nt2][3],
                      sB + bBase[nt2] + (kb ^ bSwz[nt2]));
        }
        #pragma unroll
        for (int ks = 0; ks < 4; ++ks) {
            const int cur = ks & 1, nxt = cur ^ 1;
            if (ks < 3) {
                const uint32_t kb = (ks + 1) * 32 + hi16;
                #pragma unroll
                for (int mt = 0; mt < 4; ++mt)
                    LDSM4(afr[nxt][mt][0], afr[nxt][mt][1], afr[nxt][mt][2], afr[nxt][mt][3],
                          sA + aBase[mt] + (kb ^ aSwz[mt]));
                #pragma unroll
                for (int nt2 = 0; nt2 < 2; ++nt2)
                    LDSM4(bfr[nxt][nt2][0], bfr[nxt][nt2][1], bfr[nxt][nt2][2], bfr[nxt][nt2][3],
                          sB + bBase[nt2] + (kb ^ bSwz[nt2]));
            }
            #pragma unroll
            for (int mt = 0; mt < 4; ++mt) {
                #pragma unroll
                for (int nt = 0; nt < 4; ++nt) {
                    uint32_t bfrag[2] = { bfr[cur][nt >> 1][nt & 1],
                                          bfr[cur][nt >> 1][(nt & 1) + 2] };
                    MMA16816(acc[mt][nt], afr[cur][mt], bfrag);
                }
            }
        }
    }

    // ---- epilogue: + bias[col], write C ------------------------------------
    const int group = lane >> 2;
    const int t4    = lane & 3;
    #pragma unroll
    for (int mt = 0; mt < 4; ++mt) {
        #pragma unroll
        for (int half = 0; half < 2; ++half) {
            const int row = m0 + wm * 64 + mt * 16 + group + half * 8;
            float* cp = C + (size_t)row * D_;
            #pragma unroll
            for (int nt = 0; nt < 4; ++nt) {
                const int col = n0 + wn * 32 + nt * 8 + t4 * 2;
                float2 bv = *reinterpret_cast<const float2*>(bias + col);
                float2 v;
                v.x = acc[mt][nt][half * 2]     + bv.x;
                v.y = acc[mt][nt][half * 2 + 1] + bv.y;
                *reinterpret_cast<float2*>(cp + col) = v;
            }
        }
    }
}

// ---------------------------------------------------------------------------
extern "C" void kernel_launch(void* const* d_in, const int* in_sizes, int n_in,
                              void* d_out, int out_size) {
    const float* beat = (const float*)d_in[0];   // [8, 8192, 1024]
    const float* W    = (const float*)d_in[1];   // [1024, 1056]
    const float* bias = (const float*)d_in[2];   // [1024]
    float* out = (float*)d_out;                  // [8, 2048, 1024]

    cudaFuncSetAttribute(gemm_kernel, cudaFuncAttributeMaxDynamicSharedMemorySize,
                         SMEM_TOTAL);

    pool_kernel<<<ROWS, 256>>>((const float4*)beat);
    ff_fill_kernel<<<MB_, 64>>>();
    wsplit_kernel<<<D_, 160>>>(W);
    dim3 grid(D_ / BN, ROWS / BM);               // (8, 128)
    gemm_kernel<<<grid, 256, SMEM_TOTAL>>>(out, bias);
}